// round 16
// baseline (speedup 1.0000x reference)
#include <cuda_runtime.h>
#include <math.h>

#define NQ 20
#define NSTATE (1u << NQ)
#define NPAIR 2   // batch pairs (B=4 -> 2 pairs packed into f32x2 lanes)
typedef unsigned long long ull;

// Scratch state, batch-pair packed: element = ulonglong2{ R=(re_b0,re_b1), I=(im_b0,im_b1) }
__device__ __align__(16) ulonglong2 g_bufA[(size_t)NPAIR << NQ];
__device__ __align__(16) ulonglong2 g_bufB[(size_t)NPAIR << NQ];
// Precomputed per (layer, state-bit): RX (cos(t/2), sin(t/2)) and RZ half-angles
__device__ float2 g_cs[4 * 32];
__device__ float  g_hz[4 * 32];

struct C2 { ull R, I; };

__device__ __forceinline__ ull pk2(float lo, float hi) {
    ull r; asm("mov.b64 %0,{%1,%2};" : "=l"(r) : "f"(lo), "f"(hi)); return r;
}
__device__ __forceinline__ void upk2(ull v, float& lo, float& hi) {
    asm("mov.b64 {%0,%1},%2;" : "=f"(lo), "=f"(hi) : "l"(v));
}
__device__ __forceinline__ ull dup2(float x) { return pk2(x, x); }
__device__ __forceinline__ ull f2mul(ull a, ull b) {
    ull r; asm("mul.rn.f32x2 %0,%1,%2;" : "=l"(r) : "l"(a), "l"(b)); return r;
}
__device__ __forceinline__ ull f2fma(ull a, ull b, ull c) {
    ull r; asm("fma.rn.f32x2 %0,%1,%2,%3;" : "=l"(r) : "l"(a), "l"(b), "l"(c)); return r;
}

// RX butterfly: v0' = c v0 - i s v1 ; v1' = -i s v0 + c v1
__device__ __forceinline__ void rx_bfly(C2& a, C2& b, ull cc, ull ss, ull ns) {
    ull r0 = f2fma(a.R, cc, f2mul(b.I, ss));
    ull i0 = f2fma(a.I, cc, f2mul(b.R, ns));
    ull r1 = f2fma(b.R, cc, f2mul(a.I, ss));
    ull i1 = f2fma(b.I, cc, f2mul(a.R, ns));
    a.R = r0; a.I = i0; b.R = r1; b.I = i1;
}
__device__ __forceinline__ void h_bfly(C2& a, C2& b, ull rr, ull nr) {
    ull r0 = f2fma(a.R, rr, f2mul(b.R, rr));
    ull i0 = f2fma(a.I, rr, f2mul(b.I, rr));
    ull r1 = f2fma(a.R, rr, f2mul(b.R, nr));
    ull i1 = f2fma(a.I, rr, f2mul(b.I, nr));
    a.R = r0; a.I = i0; b.R = r1; b.I = i1;
}
// v *= (f.x + i f.y)
__device__ __forceinline__ void phf(C2& a, float2 f) {
    ull cc = dup2(f.x), ss = dup2(f.y), ns = dup2(-f.y);
    ull r = f2fma(a.R, cc, f2mul(a.I, ns));
    ull i = f2fma(a.I, cc, f2mul(a.R, ss));
    a.R = r; a.I = i;
}
__device__ __forceinline__ float2 cm(float2 a, float2 b) {
    return make_float2(fmaf(a.x, b.x, -a.y * b.y), fmaf(a.x, b.y, a.y * b.x));
}

template<int K> __device__ __forceinline__ void rx_stage8(C2* v, float2 cs) {
    ull cc = dup2(cs.x), ss = dup2(cs.y), ns = dup2(-cs.y);
#pragma unroll
    for (int p = 0; p < 4; ++p) {
        int i0 = ((p >> K) << (K + 1)) | (p & ((1 << K) - 1));
        rx_bfly(v[i0], v[i0 | (1 << K)], cc, ss, ns);
    }
}
template<int K> __device__ __forceinline__ void h_stage8(C2* v) {
    const float r2 = 0.7071067811865476f;
    ull rr = dup2(r2), nr = dup2(-r2);
#pragma unroll
    for (int p = 0; p < 4; ++p) {
        int i0 = ((p >> K) << (K + 1)) | (p & ((1 << K) - 1));
        h_bfly(v[i0], v[i0 | (1 << K)], rr, nr);
    }
}
__device__ __forceinline__ void h3(C2* v) { h_stage8<0>(v); h_stage8<1>(v); h_stage8<2>(v); }
__device__ __forceinline__ void rx3s(C2* v, const float2* cs, int b0) {
    rx_stage8<0>(v, cs[b0 + 0]);
    rx_stage8<1>(v, cs[b0 + 1]);
    rx_stage8<2>(v, cs[b0 + 2]);
}

// smem swizzle: conflict-free per 8-lane phase for all access patterns used
__device__ __forceinline__ unsigned sw(unsigned t) { return t ^ ((t >> 3) & 7u); }

// cis( sum_k ±hz[l,b0+k] ) with sign from bit k of e
__device__ __forceinline__ float2 cis_bits(int l, int b0, int nb, int e) {
    float ph = 0.f;
    for (int k = 0; k < nb; ++k) {
        float t = g_hz[l * 32 + b0 + k];
        ph += ((e >> k) & 1) ? t : -t;
    }
    float s, c; sincosf(ph, &s, &c);
    return make_float2(c, s);
}

// Setup: per (layer, bit) RX coefs + RZ half angles (theta index = l*20 + (19-bit))
__global__ void k_setup(const float* __restrict__ thx, const float* __restrict__ thz) {
    int i = threadIdx.x;
    if (i < 80) {
        int l = i / 20, q = i % 20, bit = 19 - q;
        float s, c; sincosf(0.5f * thx[i], &s, &c);
        g_cs[l * 32 + bit] = make_float2(c, s);
        g_hz[l * 32 + bit] = 0.5f * thz[i];
    }
}

// ---------------------------------------------------------------------------
// LOW pass: tile = state bits 0..10 (2048 elems, 32KB), 256 thr x 8 elems.
// Rounds (coalescing-first): R0 e=8..10 (gates 8,9,10, lane-contiguous global),
// R1 e=0..2, R2 e=3..5, R3 e=6..8 (gates 6,7) + contiguous store.
// HG: layer-0 (H + per-round RZ slice). Else full local RZ phase in R0.
// FO: final gray-decode scatter of REAL parts into fout.
// PDL: preamble builds tables from g_hz/g_cs (safe pre-gridsync: k_setup
// completed before P1), then cudaGridDependencySynchronize, then state loads.
// ---------------------------------------------------------------------------
template<bool HG, bool PL, bool FO>
__global__ void __launch_bounds__(256, 5) k_low(
    const float* __restrict__ re, const float* __restrict__ im,
    int src, float* __restrict__ fout, int l)
{
    __shared__ ulonglong2 ts[2048];
    __shared__ float2 z0[8], z1[8], z8[8], z67[4];
    __shared__ float2 cs_s[11];
    const unsigned u = threadIdx.x, blk = blockIdx.x;
    const unsigned pair = blk >> 9, base = (blk & 511u) << 11;   // bits 11..19
    const size_t poff = (size_t)pair << NQ;

    const ulonglong2* __restrict__ in = (src & 1) ? g_bufB : g_bufA;
    ulonglong2* __restrict__ out = (src & 1) ? g_bufA : g_bufB;

    // Preamble (overlaps previous pass via PDL)
    if (u < 8)       z0[u]       = cis_bits(l, 0, 3, u);
    else if (u < 16) z1[u - 8]   = cis_bits(l, 3, 3, u - 8);
    else if (u < 24) z8[u - 16]  = cis_bits(l, 8, 3, u - 16);
    else if (u < 28) z67[u - 24] = cis_bits(l, 6, 2, u - 24);
    else if (u >= 32 && u < 43) cs_s[u - 32] = g_cs[l * 32 + (u - 32)];

    cudaGridDependencySynchronize();
    __syncthreads();

    C2 v[8];
    // R0: e = bits 8..10 (lane-contiguous global); gates 8,9,10
    {
        if (PL) {
            size_t b0 = ((size_t)(2 * pair) << NQ) + base + u;
#pragma unroll
            for (int e = 0; e < 8; ++e) {
                size_t idx = b0 + ((size_t)e << 8);
                v[e].R = pk2(re[idx], re[idx + NSTATE]);
                v[e].I = pk2(im[idx], im[idx + NSTATE]);
            }
        } else {
#pragma unroll
            for (int e = 0; e < 8; ++e) {
                ulonglong2 w = in[poff + base + ((unsigned)e << 8) + u];
                v[e].R = w.x; v[e].I = w.y;
            }
        }
        if (HG) {
            h3(v);
#pragma unroll
            for (int e = 0; e < 8; ++e) phf(v[e], z8[e]);
        } else {
            float2 thrf = cm(cm(z0[u & 7], z1[(u >> 3) & 7]), z67[(u >> 6) & 3]);
#pragma unroll
            for (int e = 0; e < 8; ++e) phf(v[e], cm(thrf, z8[e]));
        }
        rx3s(v, cs_s, 8);
#pragma unroll
        for (int e = 0; e < 8; ++e) ts[sw((e << 8) | u)] = make_ulonglong2(v[e].R, v[e].I);
    }
    __syncthreads();
    // R1: e = bits 0..2 ; thread u = bits 3..10
    {
        const unsigned tb = u << 3;
#pragma unroll
        for (int e = 0; e < 8; ++e) { ulonglong2 w = ts[sw(tb | e)]; v[e].R = w.x; v[e].I = w.y; }
        if (HG) {
            h3(v);
#pragma unroll
            for (int e = 0; e < 8; ++e) phf(v[e], z0[e]);
        }
        rx3s(v, cs_s, 0);
#pragma unroll
        for (int e = 0; e < 8; ++e) ts[sw(tb | e)] = make_ulonglong2(v[e].R, v[e].I);
    }
    __syncthreads();
    // R2: e = bits 3..5 ; thread: bits 0..2 = u&7, bits 6..10 = u>>3
    {
        const unsigned tb = ((u >> 3) << 6) | (u & 7u);
#pragma unroll
        for (int e = 0; e < 8; ++e) { ulonglong2 w = ts[sw(tb | (e << 3))]; v[e].R = w.x; v[e].I = w.y; }
        if (HG) {
            h3(v);
#pragma unroll
            for (int e = 0; e < 8; ++e) phf(v[e], z1[e]);
        }
        rx3s(v, cs_s, 3);
#pragma unroll
        for (int e = 0; e < 8; ++e) ts[sw(tb | (e << 3))] = make_ulonglong2(v[e].R, v[e].I);
    }
    __syncthreads();
    // R3: e = bits 6..8 (bit 8 gated in R0); gates 6,7; contiguous store
    {
        const unsigned tb = ((u >> 6) << 9) | (u & 63u);
#pragma unroll
        for (int e = 0; e < 8; ++e) { ulonglong2 w = ts[sw(tb | (e << 6))]; v[e].R = w.x; v[e].I = w.y; }
        if (HG) {
            h_stage8<0>(v); h_stage8<1>(v);
#pragma unroll
            for (int e = 0; e < 8; ++e) phf(v[e], z67[e & 3]);
        }
        rx_stage8<0>(v, cs_s[6]);
        rx_stage8<1>(v, cs_s[7]);
        if (FO) {
            // out[i] = Re(state[i ^ (i>>1)])  <=>  fout[graydecode(s)] = Re(state[s])
#pragma unroll
            for (int e = 0; e < 8; ++e) {
                unsigned s = base | tb | ((unsigned)e << 6);
                unsigned d = s; d ^= d >> 1; d ^= d >> 2; d ^= d >> 4; d ^= d >> 8; d ^= d >> 16;
                float lo, hi; upk2(v[e].R, lo, hi);
                fout[((size_t)(2 * pair) << NQ) + d] = lo;
                fout[((size_t)(2 * pair + 1) << NQ) + d] = hi;
            }
        } else {
#pragma unroll
            for (int e = 0; e < 8; ++e)
                out[poff + base + tb + ((unsigned)e << 6)] = make_ulonglong2(v[e].R, v[e].I);
        }
    }
}

// ---------------------------------------------------------------------------
// HIGH pass: gates bits 11..19. Tile local bits {0,1} U {11..19}; block fixes
// bits 2..10. GR: gray-gather input (fused CNOT chain of previous layer).
// HGATE: layer 0 (H + per-round RZ slice). Else full RZ(11..19) phase in R0.
// PDL preamble as in k_low.
// ---------------------------------------------------------------------------
template<bool HGATE, bool GR>
__global__ void __launch_bounds__(256, 5) k_high(int src, int l)
{
    __shared__ ulonglong2 ts[2048];
    __shared__ float2 zh0[8], zh1[8], zh2[8];
    __shared__ float2 cs_s[9];
    const unsigned u = threadIdx.x, blk = blockIdx.x;
    const unsigned pair = blk >> 9, mid = (blk & 511u) << 2;   // state bits 2..10
    const size_t poff = (size_t)pair << NQ;

    const ulonglong2* __restrict__ in = (src & 1) ? g_bufB : g_bufA;
    ulonglong2* __restrict__ out = (src & 1) ? g_bufA : g_bufB;

    // Preamble (overlaps previous pass via PDL)
    if (u < 8)       zh0[u]      = cis_bits(l, 11, 3, u);
    else if (u < 16) zh1[u - 8]  = cis_bits(l, 14, 3, u - 8);
    else if (u < 24) zh2[u - 16] = cis_bits(l, 17, 3, u - 16);
    else if (u >= 32 && u < 41) cs_s[u - 32] = g_cs[l * 32 + 11 + (u - 32)];

    cudaGridDependencySynchronize();
    __syncthreads();

    C2 v[8];
    const unsigned low2 = u & 3u, hi6 = u >> 2;
    const unsigned gfix = (hi6 << 14) | mid | low2;

    // R0: e = bits 11..13 : (gray gather | load) + phase + RX(11..13)
    {
#pragma unroll
        for (int e = 0; e < 8; ++e) {
            unsigned g = gfix | ((unsigned)e << 11);
            unsigned a = GR ? (g ^ (g >> 1)) : g;    // CNOT chain = binary->gray
            ulonglong2 w = in[poff + a]; v[e].R = w.x; v[e].I = w.y;
        }
        if (HGATE) {
            h3(v);
#pragma unroll
            for (int e = 0; e < 8; ++e) phf(v[e], zh0[e]);
        } else {
            float2 thrf = cm(zh1[hi6 & 7], zh2[hi6 >> 3]);
#pragma unroll
            for (int e = 0; e < 8; ++e) phf(v[e], cm(thrf, zh0[e]));
        }
        rx3s(v, cs_s, 0);
        const unsigned tb = (hi6 << 5) | low2;
#pragma unroll
        for (int e = 0; e < 8; ++e) ts[sw(tb | (e << 2))] = make_ulonglong2(v[e].R, v[e].I);
    }
    __syncthreads();
    // R1: e = bits 14..16
    {
        const unsigned tb = ((u >> 5) << 8) | (u & 31u);
#pragma unroll
        for (int e = 0; e < 8; ++e) { ulonglong2 w = ts[sw(tb | (e << 5))]; v[e].R = w.x; v[e].I = w.y; }
        if (HGATE) {
            h3(v);
#pragma unroll
            for (int e = 0; e < 8; ++e) phf(v[e], zh1[e]);
        }
        rx3s(v, cs_s, 3);
#pragma unroll
        for (int e = 0; e < 8; ++e) ts[sw(tb | (e << 5))] = make_ulonglong2(v[e].R, v[e].I);
    }
    __syncthreads();
    // R2: e = bits 17..19, store linear
    {
#pragma unroll
        for (int e = 0; e < 8; ++e) { ulonglong2 w = ts[sw((e << 8) | u)]; v[e].R = w.x; v[e].I = w.y; }
        if (HGATE) {
            h3(v);
#pragma unroll
            for (int e = 0; e < 8; ++e) phf(v[e], zh2[e]);
        }
        rx3s(v, cs_s, 6);
        const unsigned gl = mid | (u & 3u) | (((u >> 2) & 63u) << 11);
#pragma unroll
        for (int e = 0; e < 8; ++e)
            out[poff + (gl | ((unsigned)e << 17))] = make_ulonglong2(v[e].R, v[e].I);
    }
}

extern "C" void kernel_launch(void* const* d_in, const int* in_sizes, int n_in,
                              void* d_out, int out_size) {
    const float *re = nullptr, *im = nullptr, *thx = nullptr, *thz = nullptr;
    for (int i = 0; i < n_in; ++i) {
        if (in_sizes[i] > 1024) {
            if (!re) re = (const float*)d_in[i];
            else if (!im) im = (const float*)d_in[i];
        } else {
            if (!thx) thx = (const float*)d_in[i];
            else if (!thz) thz = (const float*)d_in[i];
        }
    }
    if (!re || !im || !thx || !thz) return;

    const dim3 gr(NPAIR * 512);
    const dim3 th(256);

    // PDL launch config (programmatic stream serialization) for P2..P8
    cudaLaunchConfig_t cfg = {};
    cfg.gridDim = gr; cfg.blockDim = th; cfg.dynamicSmemBytes = 0; cfg.stream = 0;
    cudaLaunchAttribute at[1];
    at[0].id = cudaLaunchAttributeProgrammaticStreamSerialization;
    at[0].val.programmaticStreamSerializationAllowed = 1;
    cfg.attrs = at; cfg.numAttrs = 1;

    k_setup<<<1, 128>>>(thx, thz);
    // P1: low : H+RZ0+RX0 (bits 0..10), planar -> A   (normal launch)
    k_low<true, true, false><<<gr, th>>>(re, im, 1, (float*)nullptr, 0);
    // P2: high : H+RZ0+RX0 (bits 11..19)      A -> B
    cudaLaunchKernelEx(&cfg, k_high<true, false>, 0, 0);
    // P3: high : gray0 + RZ1+RX1 (hi)         B -> A
    cudaLaunchKernelEx(&cfg, k_high<false, true>, 1, 1);
    // P4: low : RZ1+RX1 (lo)                  A -> B
    cudaLaunchKernelEx(&cfg, k_low<false, false, false>,
                       (const float*)nullptr, (const float*)nullptr, 0, (float*)nullptr, 1);
    // P5: high : gray1 + RZ2+RX2 (hi)         B -> A
    cudaLaunchKernelEx(&cfg, k_high<false, true>, 1, 2);
    // P6: low : RZ2+RX2 (lo)                  A -> B
    cudaLaunchKernelEx(&cfg, k_low<false, false, false>,
                       (const float*)nullptr, (const float*)nullptr, 0, (float*)nullptr, 2);
    // P7: high : gray2 + RZ3+RX3 (hi)         B -> A
    cudaLaunchKernelEx(&cfg, k_high<false, true>, 1, 3);
    // P8: low : RZ3+RX3 (lo) + gray3 scatter of REAL parts -> d_out
    cudaLaunchKernelEx(&cfg, k_low<false, false, true>,
                       (const float*)nullptr, (const float*)nullptr, 0, (float*)d_out, 3);
}

// round 17
// speedup vs baseline: 1.1914x; 1.1914x over previous
#include <cuda_runtime.h>
#include <math.h>

#define NQ 20
#define NSTATE (1u << NQ)
typedef unsigned long long ull;

// Scratch state, batch-pair packed: element = ulonglong2{ R=(re_b0,re_b1), I=(im_b0,im_b1) }
__device__ __align__(16) ulonglong2 g_bufA[(size_t)2 << NQ];
__device__ __align__(16) ulonglong2 g_bufB[(size_t)2 << NQ];

struct C2 { ull R, I; };

__device__ __forceinline__ ull pk2(float lo, float hi) {
    ull r; asm("mov.b64 %0,{%1,%2};" : "=l"(r) : "f"(lo), "f"(hi)); return r;
}
__device__ __forceinline__ void upk2(ull v, float& lo, float& hi) {
    asm("mov.b64 {%0,%1},%2;" : "=f"(lo), "=f"(hi) : "l"(v));
}
__device__ __forceinline__ ull dup2(float x) { return pk2(x, x); }
__device__ __forceinline__ ull f2mul(ull a, ull b) {
    ull r; asm("mul.rn.f32x2 %0,%1,%2;" : "=l"(r) : "l"(a), "l"(b)); return r;
}
__device__ __forceinline__ ull f2fma(ull a, ull b, ull c) {
    ull r; asm("fma.rn.f32x2 %0,%1,%2,%3;" : "=l"(r) : "l"(a), "l"(b), "l"(c)); return r;
}

// RX butterfly: v0' = c v0 - i s v1 ; v1' = -i s v0 + c v1
__device__ __forceinline__ void rx_bfly(C2& a, C2& b, ull cc, ull ss, ull ns) {
    ull r0 = f2fma(a.R, cc, f2mul(b.I, ss));
    ull i0 = f2fma(a.I, cc, f2mul(b.R, ns));
    ull r1 = f2fma(b.R, cc, f2mul(a.I, ss));
    ull i1 = f2fma(b.I, cc, f2mul(a.R, ns));
    a.R = r0; a.I = i0; b.R = r1; b.I = i1;
}
__device__ __forceinline__ void h_bfly(C2& a, C2& b, ull rr, ull nr) {
    ull r0 = f2fma(a.R, rr, f2mul(b.R, rr));
    ull i0 = f2fma(a.I, rr, f2mul(b.I, rr));
    ull r1 = f2fma(a.R, rr, f2mul(b.R, nr));
    ull i1 = f2fma(a.I, rr, f2mul(b.I, nr));
    a.R = r0; a.I = i0; b.R = r1; b.I = i1;
}
// v *= (f.x + i f.y)
__device__ __forceinline__ void phf(C2& a, float2 f) {
    ull cc = dup2(f.x), ss = dup2(f.y), ns = dup2(-f.y);
    ull r = f2fma(a.R, cc, f2mul(a.I, ns));
    ull i = f2fma(a.I, cc, f2mul(a.R, ss));
    a.R = r; a.I = i;
}
__device__ __forceinline__ float2 cm(float2 a, float2 b) {
    return make_float2(fmaf(a.x, b.x, -a.y * b.y), fmaf(a.x, b.y, a.y * b.x));
}

template<int K> __device__ __forceinline__ void rx_stage8(C2* v, float2 cs) {
    ull cc = dup2(cs.x), ss = dup2(cs.y), ns = dup2(-cs.y);
#pragma unroll
    for (int p = 0; p < 4; ++p) {
        int i0 = ((p >> K) << (K + 1)) | (p & ((1 << K) - 1));
        rx_bfly(v[i0], v[i0 | (1 << K)], cc, ss, ns);
    }
}
template<int K> __device__ __forceinline__ void h_stage8(C2* v) {
    const float r2 = 0.7071067811865476f;
    ull rr = dup2(r2), nr = dup2(-r2);
#pragma unroll
    for (int p = 0; p < 4; ++p) {
        int i0 = ((p >> K) << (K + 1)) | (p & ((1 << K) - 1));
        h_bfly(v[i0], v[i0 | (1 << K)], rr, nr);
    }
}
__device__ __forceinline__ void h3(C2* v) { h_stage8<0>(v); h_stage8<1>(v); h_stage8<2>(v); }
__device__ __forceinline__ void rx3s(C2* v, const float2* cs, int b0) {
    rx_stage8<0>(v, cs[b0 + 0]);
    rx_stage8<1>(v, cs[b0 + 1]);
    rx_stage8<2>(v, cs[b0 + 2]);
}

// smem swizzle: conflict-free per 8-lane phase for all access patterns used
__device__ __forceinline__ unsigned sw(unsigned t) { return t ^ ((t >> 3) & 7u); }

// cis( sum_k ±0.5*thz[l,qubit(b0+k)] ) with sign from bit k of e  (qubit = 19-bit)
__device__ __forceinline__ float2 cisb(const float* __restrict__ thz, int l, int b0, int nb, int e) {
    float ph = 0.f;
    for (int k = 0; k < nb; ++k) {
        float t = 0.5f * thz[l * 20 + 19 - (b0 + k)];
        ph += ((e >> k) & 1) ? t : -t;
    }
    float s, c; sincosf(ph, &s, &c);
    return make_float2(c, s);
}
// RX coefficients (cos, sin of half angle) for global bit b
__device__ __forceinline__ float2 rxc(const float* __restrict__ thx, int l, int b) {
    float s, c; sincosf(0.5f * thx[l * 20 + 19 - b], &s, &c);
    return make_float2(c, s);
}

// ---------------------------------------------------------------------------
// LOW pass (one batch-pair): tile = state bits 0..10 (2048 elems, 32KB),
// 512 blocks x 256 thr x 8 elems. Rounds: R0 e=8..10 (gates 8,9,10, coalesced
// global), R1 e=0..2, R2 e=3..5, R3 e=6..8 (gates 6,7) + contiguous store.
// HG: layer-0 (H + per-round RZ slice). Else full local RZ phase in R0.
// FO: final gray-decode scatter of REAL parts into fout.
// PDL: preamble builds tables from raw thetas, then gridsync, then state I/O.
// ---------------------------------------------------------------------------
template<bool HG, bool PL, bool FO>
__global__ void __launch_bounds__(256, 5) k_low(
    const float* __restrict__ re, const float* __restrict__ im,
    const float* __restrict__ thx, const float* __restrict__ thz,
    int pair, int src, float* __restrict__ fout, int l)
{
    __shared__ ulonglong2 ts[2048];
    __shared__ float2 z0[8], z1[8], z8[8], z67[4];
    __shared__ float2 cs_s[11];
    const unsigned u = threadIdx.x;
    const unsigned base = blockIdx.x << 11;            // bits 11..19 (512 blocks)
    const size_t poff = (size_t)pair << NQ;

    const ulonglong2* __restrict__ in = (src & 1) ? g_bufB : g_bufA;
    ulonglong2* __restrict__ out = (src & 1) ? g_bufA : g_bufB;

    // Preamble (overlaps previous pass via PDL)
    if (u < 8)       z0[u]       = cisb(thz, l, 0, 3, u);
    else if (u < 16) z1[u - 8]   = cisb(thz, l, 3, 3, u - 8);
    else if (u < 24) z8[u - 16]  = cisb(thz, l, 8, 3, u - 16);
    else if (u < 28) z67[u - 24] = cisb(thz, l, 6, 2, u - 24);
    else if (u >= 32 && u < 43) cs_s[u - 32] = rxc(thx, l, u - 32);

    cudaGridDependencySynchronize();
    __syncthreads();

    C2 v[8];
    // R0: e = bits 8..10 (lane-contiguous global); gates 8,9,10
    {
        if (PL) {
            size_t b0 = ((size_t)(2 * pair) << NQ) + base + u;
#pragma unroll
            for (int e = 0; e < 8; ++e) {
                size_t idx = b0 + ((size_t)e << 8);
                v[e].R = pk2(re[idx], re[idx + NSTATE]);
                v[e].I = pk2(im[idx], im[idx + NSTATE]);
            }
        } else {
#pragma unroll
            for (int e = 0; e < 8; ++e) {
                ulonglong2 w = in[poff + base + ((unsigned)e << 8) + u];
                v[e].R = w.x; v[e].I = w.y;
            }
        }
        if (HG) {
            h3(v);
#pragma unroll
            for (int e = 0; e < 8; ++e) phf(v[e], z8[e]);
        } else {
            float2 thrf = cm(cm(z0[u & 7], z1[(u >> 3) & 7]), z67[(u >> 6) & 3]);
#pragma unroll
            for (int e = 0; e < 8; ++e) phf(v[e], cm(thrf, z8[e]));
        }
        rx3s(v, cs_s, 8);
#pragma unroll
        for (int e = 0; e < 8; ++e) ts[sw((e << 8) | u)] = make_ulonglong2(v[e].R, v[e].I);
    }
    __syncthreads();
    // R1: e = bits 0..2 ; thread u = bits 3..10
    {
        const unsigned tb = u << 3;
#pragma unroll
        for (int e = 0; e < 8; ++e) { ulonglong2 w = ts[sw(tb | e)]; v[e].R = w.x; v[e].I = w.y; }
        if (HG) {
            h3(v);
#pragma unroll
            for (int e = 0; e < 8; ++e) phf(v[e], z0[e]);
        }
        rx3s(v, cs_s, 0);
#pragma unroll
        for (int e = 0; e < 8; ++e) ts[sw(tb | e)] = make_ulonglong2(v[e].R, v[e].I);
    }
    __syncthreads();
    // R2: e = bits 3..5 ; thread: bits 0..2 = u&7, bits 6..10 = u>>3
    {
        const unsigned tb = ((u >> 3) << 6) | (u & 7u);
#pragma unroll
        for (int e = 0; e < 8; ++e) { ulonglong2 w = ts[sw(tb | (e << 3))]; v[e].R = w.x; v[e].I = w.y; }
        if (HG) {
            h3(v);
#pragma unroll
            for (int e = 0; e < 8; ++e) phf(v[e], z1[e]);
        }
        rx3s(v, cs_s, 3);
#pragma unroll
        for (int e = 0; e < 8; ++e) ts[sw(tb | (e << 3))] = make_ulonglong2(v[e].R, v[e].I);
    }
    __syncthreads();
    // R3: e = bits 6..8 (bit 8 gated in R0); gates 6,7; contiguous store
    {
        const unsigned tb = ((u >> 6) << 9) | (u & 63u);
#pragma unroll
        for (int e = 0; e < 8; ++e) { ulonglong2 w = ts[sw(tb | (e << 6))]; v[e].R = w.x; v[e].I = w.y; }
        if (HG) {
            h_stage8<0>(v); h_stage8<1>(v);
#pragma unroll
            for (int e = 0; e < 8; ++e) phf(v[e], z67[e & 3]);
        }
        rx_stage8<0>(v, cs_s[6]);
        rx_stage8<1>(v, cs_s[7]);
        if (FO) {
            // out[i] = Re(state[i ^ (i>>1)])  <=>  fout[graydecode(s)] = Re(state[s])
#pragma unroll
            for (int e = 0; e < 8; ++e) {
                unsigned s = base | tb | ((unsigned)e << 6);
                unsigned d = s; d ^= d >> 1; d ^= d >> 2; d ^= d >> 4; d ^= d >> 8; d ^= d >> 16;
                float lo, hi; upk2(v[e].R, lo, hi);
                fout[((size_t)(2 * pair) << NQ) + d] = lo;
                fout[((size_t)(2 * pair + 1) << NQ) + d] = hi;
            }
        } else {
#pragma unroll
            for (int e = 0; e < 8; ++e)
                out[poff + base + tb + ((unsigned)e << 6)] = make_ulonglong2(v[e].R, v[e].I);
        }
    }
    cudaTriggerProgrammaticLaunchCompletion();
}

// ---------------------------------------------------------------------------
// HIGH pass (one batch-pair): gates bits 11..19. Tile local bits {0,1} U
// {11..19}; block fixes bits 2..10 (512 blocks). GR: gray-gather input (fused
// CNOT chain of previous layer). HGATE: layer 0. PDL preamble as in k_low.
// ---------------------------------------------------------------------------
template<bool HGATE, bool GR>
__global__ void __launch_bounds__(256, 5) k_high(
    const float* __restrict__ thx, const float* __restrict__ thz,
    int pair, int src, int l)
{
    __shared__ ulonglong2 ts[2048];
    __shared__ float2 zh0[8], zh1[8], zh2[8];
    __shared__ float2 cs_s[9];
    const unsigned u = threadIdx.x;
    const unsigned mid = blockIdx.x << 2;              // state bits 2..10
    const size_t poff = (size_t)pair << NQ;

    const ulonglong2* __restrict__ in = (src & 1) ? g_bufB : g_bufA;
    ulonglong2* __restrict__ out = (src & 1) ? g_bufA : g_bufB;

    // Preamble (overlaps previous pass via PDL)
    if (u < 8)       zh0[u]      = cisb(thz, l, 11, 3, u);
    else if (u < 16) zh1[u - 8]  = cisb(thz, l, 14, 3, u - 8);
    else if (u < 24) zh2[u - 16] = cisb(thz, l, 17, 3, u - 16);
    else if (u >= 32 && u < 41) cs_s[u - 32] = rxc(thx, l, 11 + (u - 32));

    cudaGridDependencySynchronize();
    __syncthreads();

    C2 v[8];
    const unsigned low2 = u & 3u, hi6 = u >> 2;
    const unsigned gfix = (hi6 << 14) | mid | low2;

    // R0: e = bits 11..13 : (gray gather | load) + phase + RX(11..13)
    {
#pragma unroll
        for (int e = 0; e < 8; ++e) {
            unsigned g = gfix | ((unsigned)e << 11);
            unsigned a = GR ? (g ^ (g >> 1)) : g;    // CNOT chain = binary->gray
            ulonglong2 w = in[poff + a]; v[e].R = w.x; v[e].I = w.y;
        }
        if (HGATE) {
            h3(v);
#pragma unroll
            for (int e = 0; e < 8; ++e) phf(v[e], zh0[e]);
        } else {
            float2 thrf = cm(zh1[hi6 & 7], zh2[hi6 >> 3]);
#pragma unroll
            for (int e = 0; e < 8; ++e) phf(v[e], cm(thrf, zh0[e]));
        }
        rx3s(v, cs_s, 0);
        const unsigned tb = (hi6 << 5) | low2;
#pragma unroll
        for (int e = 0; e < 8; ++e) ts[sw(tb | (e << 2))] = make_ulonglong2(v[e].R, v[e].I);
    }
    __syncthreads();
    // R1: e = bits 14..16
    {
        const unsigned tb = ((u >> 5) << 8) | (u & 31u);
#pragma unroll
        for (int e = 0; e < 8; ++e) { ulonglong2 w = ts[sw(tb | (e << 5))]; v[e].R = w.x; v[e].I = w.y; }
        if (HGATE) {
            h3(v);
#pragma unroll
            for (int e = 0; e < 8; ++e) phf(v[e], zh1[e]);
        }
        rx3s(v, cs_s, 3);
#pragma unroll
        for (int e = 0; e < 8; ++e) ts[sw(tb | (e << 5))] = make_ulonglong2(v[e].R, v[e].I);
    }
    __syncthreads();
    // R2: e = bits 17..19, store linear
    {
#pragma unroll
        for (int e = 0; e < 8; ++e) { ulonglong2 w = ts[sw((e << 8) | u)]; v[e].R = w.x; v[e].I = w.y; }
        if (HGATE) {
            h3(v);
#pragma unroll
            for (int e = 0; e < 8; ++e) phf(v[e], zh2[e]);
        }
        rx3s(v, cs_s, 6);
        const unsigned gl = mid | (u & 3u) | (((u >> 2) & 63u) << 11);
#pragma unroll
        for (int e = 0; e < 8; ++e)
            out[poff + (gl | ((unsigned)e << 17))] = make_ulonglong2(v[e].R, v[e].I);
    }
    cudaTriggerProgrammaticLaunchCompletion();
}

extern "C" void kernel_launch(void* const* d_in, const int* in_sizes, int n_in,
                              void* d_out, int out_size) {
    const float *re = nullptr, *im = nullptr, *thx = nullptr, *thz = nullptr;
    for (int i = 0; i < n_in; ++i) {
        if (in_sizes[i] > 1024) {
            if (!re) re = (const float*)d_in[i];
            else if (!im) im = (const float*)d_in[i];
        } else {
            if (!thx) thx = (const float*)d_in[i];
            else if (!thz) thz = (const float*)d_in[i];
        }
    }
    if (!re || !im || !thx || !thz) return;
    float* fout = (float*)d_out;

    // Fork a second stream off the (captured) default stream: the two
    // batch-pair chains are fully independent. Streams/events are created
    // fresh each call (capture-legal) and intentionally not destroyed while
    // capture is active.
    cudaStream_t s2;
    cudaStreamCreateWithFlags(&s2, cudaStreamNonBlocking);
    cudaEvent_t evF, evJ;
    cudaEventCreateWithFlags(&evF, cudaEventDisableTiming);
    cudaEventCreateWithFlags(&evJ, cudaEventDisableTiming);
    cudaEventRecord(evF, 0);
    cudaStreamWaitEvent(s2, evF, 0);

    const dim3 gr(512);
    const dim3 th(256);

    cudaLaunchAttribute at[1];
    at[0].id = cudaLaunchAttributeProgrammaticStreamSerialization;
    at[0].val.programmaticStreamSerializationAllowed = 1;

    for (int pair = 0; pair < 2; ++pair) {
        cudaLaunchConfig_t cfg = {};
        cfg.gridDim = gr; cfg.blockDim = th; cfg.dynamicSmemBytes = 0;
        cfg.stream = (pair == 0) ? (cudaStream_t)0 : s2;
        cfg.attrs = at; cfg.numAttrs = 1;

        // P1: low : H+RZ0+RX0 (bits 0..10), planar -> A
        cudaLaunchKernelEx(&cfg, k_low<true, true, false>,
                           re, im, thx, thz, pair, 1, (float*)nullptr, 0);
        // P2: high : H+RZ0+RX0 (bits 11..19)      A -> B
        cudaLaunchKernelEx(&cfg, k_high<true, false>, thx, thz, pair, 0, 0);
        // P3: high : gray0 + RZ1+RX1 (hi)         B -> A
        cudaLaunchKernelEx(&cfg, k_high<false, true>, thx, thz, pair, 1, 1);
        // P4: low : RZ1+RX1 (lo)                  A -> B
        cudaLaunchKernelEx(&cfg, k_low<false, false, false>,
                           (const float*)nullptr, (const float*)nullptr, thx, thz,
                           pair, 0, (float*)nullptr, 1);
        // P5: high : gray1 + RZ2+RX2 (hi)         B -> A
        cudaLaunchKernelEx(&cfg, k_high<false, true>, thx, thz, pair, 1, 2);
        // P6: low : RZ2+RX2 (lo)                  A -> B
        cudaLaunchKernelEx(&cfg, k_low<false, false, false>,
                           (const float*)nullptr, (const float*)nullptr, thx, thz,
                           pair, 0, (float*)nullptr, 2);
        // P7: high : gray2 + RZ3+RX3 (hi)         B -> A
        cudaLaunchKernelEx(&cfg, k_high<false, true>, thx, thz, pair, 1, 3);
        // P8: low : RZ3+RX3 (lo) + gray3 scatter of REAL parts -> d_out
        cudaLaunchKernelEx(&cfg, k_low<false, false, true>,
                           (const float*)nullptr, (const float*)nullptr, thx, thz,
                           pair, 0, fout, 3);
    }

    // Join the forked stream back into the captured stream.
    cudaEventRecord(evJ, s2);
    cudaStreamWaitEvent((cudaStream_t)0, evJ, 0);
}